// round 5
// baseline (speedup 1.0000x reference)
#include <cuda_runtime.h>
#include <math.h>

#define NB 512      // batch
#define NT 20       // time
#define NOBJ 36
#define ND 2048
#define NEMB 300
#define NE 512
#define NHM 1024
#define NHO 256

constexpr int BT   = NB * NT;        // 10240
constexpr int KAM  = 832;            // E+EMB=812 padded to mult of 32
constexpr int KAO  = 1344;           // 2E+EMB=1324 padded
constexpr int GM4  = 4 * NHM;        // 4096
constexpr int GO4  = 4 * NHO;        // 1024
constexpr int LDW_M = NE + NEMB + ND;        // 2860
constexpr int LDW_O = 2 * NE + NEMB + ND;    // 3372

// ---------------- scratch layout ----------------
constexpr size_t OFF_MASK = 0;
constexpr size_t OFF_MEAN = OFF_MASK + (size_t)NB * NOBJ;
constexpr size_t OFF_AM   = OFF_MEAN + (size_t)NB * ND;
constexpr size_t OFF_AO   = OFF_AM   + (size_t)BT * KAM;
constexpr size_t OFF_GM   = OFF_AO   + (size_t)BT * KAO;
constexpr size_t OFF_GO   = OFF_GM   + (size_t)BT * GM4;
constexpr size_t OFF_FM   = OFF_GO   + (size_t)BT * GO4;
constexpr size_t OFF_FO   = OFF_FM   + (size_t)NB * GM4;
constexpr size_t OFF_HMA  = OFF_FO   + (size_t)NB * GO4;   // h_m ping
constexpr size_t OFF_HMB  = OFF_HMA  + (size_t)NB * NHM;   // h_m pong
constexpr size_t OFF_CM   = OFF_HMB  + (size_t)NB * NHM;
constexpr size_t OFF_HOA  = OFF_CM   + (size_t)NB * NHM;
constexpr size_t OFF_HOB  = OFF_HOA  + (size_t)NB * NHO;
constexpr size_t OFF_CO   = OFF_HOB  + (size_t)NB * NHO;
constexpr size_t OFF_HMS  = OFF_CO   + (size_t)NB * NHO;
constexpr size_t OFF_HOS  = OFF_HMS  + (size_t)BT * NHM;
constexpr size_t OFF_OUTM = OFF_HOS  + (size_t)BT * NHO;
constexpr size_t OFF_OUTO = OFF_OUTM + (size_t)BT * 2 * NE;
constexpr size_t OFF_WIM  = OFF_OUTO + (size_t)BT * 2 * NE;   // gate-interleaved W_ih_m
constexpr size_t OFF_WIO  = OFF_WIM  + (size_t)GM4 * LDW_M;
constexpr size_t OFF_WHM  = OFF_WIO  + (size_t)GO4 * LDW_O;
constexpr size_t OFF_WHO  = OFF_WHM  + (size_t)GM4 * NHM;
constexpr size_t OFF_BM   = OFF_WHO  + (size_t)GO4 * NHO;
constexpr size_t OFF_BO   = OFF_BM   + GM4;
constexpr size_t TOTAL    = OFF_BO   + GO4;

__device__ float d_scratch[TOTAL];

// =====================================================================
// tf32 tensor-core GEMM core: 128x128 block, k-tile 32, 8 warps 64x32,
// mma.m16n8k8.tf32, double-buffered smem (one barrier per k-tile).
// Fragment-major smem planes, stride 33 (conflict-free frag LDS).
// =====================================================================
#define APLANE 1056   // 8 m-tiles * 4 ik * 33
#define BPLANE 2112   // 16 n-tiles * 4 ik * 33
#define SBUF   (4 * APLANE + 2 * BPLANE)   // 8448 floats per buffer
#define DYNSMEM (2 * SBUF * 4)             // 67584 bytes (== 128*132*4 staging)

__device__ __forceinline__ unsigned f2tf32(float f) {
    unsigned u;
    asm("cvt.rna.tf32.f32 %0, %1;" : "=r"(u) : "f"(f));
    return u;
}

__device__ __forceinline__ void mma_tf32(float* d, const unsigned* a, const unsigned* b) {
    asm volatile(
        "mma.sync.aligned.m16n8k8.row.col.f32.tf32.tf32.f32 "
        "{%0,%1,%2,%3}, {%4,%5,%6,%7}, {%8,%9}, {%0,%1,%2,%3};"
        : "+f"(d[0]), "+f"(d[1]), "+f"(d[2]), "+f"(d[3])
        : "r"(a[0]), "r"(a[1]), "r"(a[2]), "r"(a[3]), "r"(b[0]), "r"(b[1]));
}

__device__ __forceinline__ void sts_tiles(float* buf, int tid,
                                          const float4* sa, const float4* sb)
{
    float* As = buf;
    float* Bs = buf + 4 * APLANE;
#pragma unroll
    for (int q = 0; q < 4; q++) {
        int v = tid + q * 256;
        int row = v >> 3, f4 = v & 7;
        {
            int im = row >> 4, r = row & 15;
            int g = r & 7, hi = r >> 3;
            int ik = f4 >> 1, chalf = f4 & 1;
            float* pl = As + (hi + 2 * chalf) * APLANE + (im * 4 + ik) * 33 + g * 4;
            pl[0] = __uint_as_float(f2tf32(sa[q].x));
            pl[1] = __uint_as_float(f2tf32(sa[q].y));
            pl[2] = __uint_as_float(f2tf32(sa[q].z));
            pl[3] = __uint_as_float(f2tf32(sa[q].w));
        }
        {
            int jn = row >> 3, n8 = row & 7;
            int ik = f4 >> 1, reg = f4 & 1;
            float* pl = Bs + reg * BPLANE + (jn * 4 + ik) * 33 + n8 * 4;
            pl[0] = __uint_as_float(f2tf32(sb[q].x));
            pl[1] = __uint_as_float(f2tf32(sb[q].y));
            pl[2] = __uint_as_float(f2tf32(sb[q].z));
            pl[3] = __uint_as_float(f2tf32(sb[q].w));
        }
    }
}

// A points at block row (bm), W at block col row (bn). acc zero-inited here.
// NOTE: no trailing __syncthreads after last compute; caller must sync
// before reusing smem.
__device__ __forceinline__ void gemm_core(
    const float* __restrict__ A, int lda,
    const float* __restrict__ W, int ldw, int K,
    float* dyn, int tid, float acc[4][4][4])
{
    const int lane = tid & 31;
    const int w = tid >> 5;
    const int wm = w & 1;
    const int wn = w >> 1;

#pragma unroll
    for (int i = 0; i < 4; i++)
#pragma unroll
        for (int j = 0; j < 4; j++)
#pragma unroll
            for (int r = 0; r < 4; r++) acc[i][j][r] = 0.f;

    float4 sa[4], sb[4];
#pragma unroll
    for (int q = 0; q < 4; q++) {
        int v = tid + q * 256;
        int row = v >> 3, f4 = v & 7;
        sa[q] = *(const float4*)(A + (size_t)row * lda + f4 * 4);
        sb[q] = *(const float4*)(W + (size_t)row * ldw + f4 * 4);
    }
    sts_tiles(dyn, tid, sa, sb);
    __syncthreads();

    const int KT = K / 32;
    for (int kt = 0; kt < KT; kt++) {
        float* sbuf = dyn + (kt & 1) * SBUF;
        const bool more = (kt + 1 < KT);
        if (more) {
            int k0 = (kt + 1) * 32;
#pragma unroll
            for (int q = 0; q < 4; q++) {
                int v = tid + q * 256;
                int row = v >> 3, f4 = v & 7;
                sa[q] = *(const float4*)(A + (size_t)row * lda + k0 + f4 * 4);
                sb[q] = *(const float4*)(W + (size_t)row * ldw + k0 + f4 * 4);
            }
        }

        float* As = sbuf;
        float* Bs = sbuf + 4 * APLANE;
#pragma unroll
        for (int ik = 0; ik < 4; ik++) {
            unsigned af[4][4], bf[4][2];
#pragma unroll
            for (int il = 0; il < 4; il++) {
                int blk = ((wm * 4 + il) * 4 + ik) * 33 + lane;
                af[il][0] = __float_as_uint(As[0 * APLANE + blk]);
                af[il][1] = __float_as_uint(As[1 * APLANE + blk]);
                af[il][2] = __float_as_uint(As[2 * APLANE + blk]);
                af[il][3] = __float_as_uint(As[3 * APLANE + blk]);
            }
#pragma unroll
            for (int jl = 0; jl < 4; jl++) {
                int blk = ((wn * 4 + jl) * 4 + ik) * 33 + lane;
                bf[jl][0] = __float_as_uint(Bs[0 * BPLANE + blk]);
                bf[jl][1] = __float_as_uint(Bs[1 * BPLANE + blk]);
            }
#pragma unroll
            for (int il = 0; il < 4; il++)
#pragma unroll
                for (int jl = 0; jl < 4; jl++)
                    mma_tf32(acc[il][jl], af[il], bf[jl]);
        }

        if (more) {
            sts_tiles(dyn + ((kt + 1) & 1) * SBUF, tid, sa, sb);
            __syncthreads();
        }
    }
}

// ---------------- standalone GEMM: C = A@W^T (+bias) (+F[row/fdiv]) -------
__global__ __launch_bounds__(256) void gemm_tf32(
    const float* __restrict__ A, int lda,
    const float* __restrict__ W, int ldw,
    float* __restrict__ C, int ldc,
    int K, const float* __restrict__ bias,
    const float* __restrict__ F, int fdiv)
{
    extern __shared__ float dyn[];
    const int tid = threadIdx.x;
    const int lane = tid & 31;
    const int w = tid >> 5, wm = w & 1, wn = w >> 1;
    const long bm = (long)blockIdx.y * 128;
    const long bn = (long)blockIdx.x * 128;

    float acc[4][4][4];
    gemm_core(A + bm * (size_t)lda, lda, W + bn * (size_t)ldw, ldw, K, dyn, tid, acc);

    const int g = lane >> 2;
    const int cp = (lane & 3) * 2;
#pragma unroll
    for (int jl = 0; jl < 4; jl++) {
        long col = bn + wn * 32 + jl * 8 + cp;
        float b0 = 0.f, b1 = 0.f;
        if (bias) { b0 = bias[col]; b1 = bias[col + 1]; }
#pragma unroll
        for (int il = 0; il < 4; il++) {
            long row = bm + wm * 64 + il * 16 + g;
            float a0 = b0, a1 = b1, a2 = b0, a3 = b1;
            if (F) {
                long fb0 = row / fdiv, fb1 = (row + 8) / fdiv;
                a0 += F[fb0 * ldc + col];     a1 += F[fb0 * ldc + col + 1];
                a2 += F[fb1 * ldc + col];     a3 += F[fb1 * ldc + col + 1];
            }
            *(float2*)(C + row * (long)ldc + col) =
                make_float2(acc[il][jl][0] + a0, acc[il][jl][1] + a1);
            *(float2*)(C + (row + 8) * (long)ldc + col) =
                make_float2(acc[il][jl][2] + a2, acc[il][jl][3] + a3);
        }
    }
}

// ---------------- fused LSTM step: R-gemm + cell, m and o LSTMs ----------
__device__ __forceinline__ float sigmoidf(float v) { return 1.f / (1.f + __expf(-v)); }

// stage acc into smem, add G (gate-interleaved), apply cell, write h/c.
__device__ __forceinline__ void cell_epilogue(
    float acc[4][4][4], float* dyn, int tid,
    const float* __restrict__ G, float* __restrict__ c,
    float* __restrict__ h_out, float* __restrict__ Hseq,
    long bm, int bx, int H, int t)
{
    const int lane = tid & 31;
    const int w = tid >> 5, wm = w & 1, wn = w >> 1;
    const int g = lane >> 2;
    const int cp = (lane & 3) * 2;

    __syncthreads();   // all warps done reading gemm smem
#pragma unroll
    for (int jl = 0; jl < 4; jl++) {
        int coll = wn * 32 + jl * 8 + cp;
#pragma unroll
        for (int il = 0; il < 4; il++) {
            int r0 = wm * 64 + il * 16 + g;
            *(float2*)&dyn[r0 * 132 + coll] =
                make_float2(acc[il][jl][0], acc[il][jl][1]);
            *(float2*)&dyn[(r0 + 8) * 132 + coll] =
                make_float2(acc[il][jl][2], acc[il][jl][3]);
        }
    }
    __syncthreads();

    const int H4 = 4 * H;
#pragma unroll 4
    for (int it = 0; it < 16; it++) {
        int cellid = tid + it * 256;
        int r = cellid >> 5, ul = cellid & 31;
        long b = bm + r;
        int u = bx * 32 + ul;
        float4 a4 = *(const float4*)&dyn[r * 132 + ul * 4];
        const float4 G4 = *(const float4*)&G[(b * NT + t) * (size_t)H4 + (size_t)bx * 128 + ul * 4];
        float gi = a4.x + G4.x;
        float gf = a4.y + G4.y;
        float gg = a4.z + G4.z;
        float go = a4.w + G4.w;
        size_t si = (size_t)b * H + u;
        float cn = sigmoidf(gf) * c[si] + sigmoidf(gi) * tanhf(gg);
        float hn = sigmoidf(go) * tanhf(cn);
        c[si] = cn;
        h_out[si] = hn;
        Hseq[(b * NT + t) * (size_t)H + u] = hn;
    }
    __syncthreads();   // protect staging before any further smem reuse
}

__global__ __launch_bounds__(256) void lstm_step(
    const float* __restrict__ hmi, float* __restrict__ hmo, float* __restrict__ cm,
    const float* __restrict__ Whm, const float* __restrict__ Gm, float* __restrict__ Hms,
    const float* __restrict__ hoi, float* __restrict__ hoo, float* __restrict__ co,
    const float* __restrict__ Who, const float* __restrict__ Go, float* __restrict__ Hos,
    int t)
{
    extern __shared__ float dyn[];
    const int tid = threadIdx.x;
    const int bx = blockIdx.x;             // 0..31
    const long bm = (long)blockIdx.y * 128;

    // ---- m LSTM: N=4096 (32 col tiles), K=1024 ----
    {
        float acc[4][4][4];
        gemm_core(hmi + bm * NHM, NHM, Whm + (size_t)bx * 128 * NHM, NHM,
                  NHM, dyn, tid, acc);
        cell_epilogue(acc, dyn, tid, Gm, cm, hmo, Hms, bm, bx, NHM, t);
    }

    // ---- o LSTM: N=1024 (8 col tiles), K=256; blocks bx<8 ----
    if (bx < 8) {
        float acc[4][4][4];
        gemm_core(hoi + bm * NHO, NHO, Who + (size_t)bx * 128 * NHO, NHO,
                  NHO, dyn, tid, acc);
        cell_epilogue(acc, dyn, tid, Go, co, hoo, Hos, bm, bx, NHO, t);
    }
}

// ---------------- weight reorder: dst row 4u+g = src row g*H+u ----------
__global__ void reorder_gates(const float* __restrict__ src, float* __restrict__ dst,
                              int H, int ldw)
{
    int r = blockIdx.x;            // 0..4H-1
    int u = r >> 2, g = r & 3;
    const float4* s = (const float4*)(src + (size_t)(g * H + u) * ldw);
    float4* d = (float4*)(dst + (size_t)r * ldw);
    for (int k = threadIdx.x; k < ldw / 4; k += blockDim.x) d[k] = s[k];
}

__global__ void reorder_bias(const float* __restrict__ src, float* __restrict__ dst, int H)
{
    int r = blockIdx.x * blockDim.x + threadIdx.x;
    if (r < 4 * H) { int u = r >> 2, g = r & 3; dst[r] = src[g * H + u]; }
}

// ---------------- small kernels ----------------
__global__ void objmask_kernel(const float* __restrict__ obj, float* __restrict__ mask)
{
    int bn = blockIdx.x;
    const float* p = obj + (size_t)bn * ND;
    float s = 0.f;
    for (int d = threadIdx.x; d < ND; d += blockDim.x) s += fabsf(p[d]);
    __shared__ float sm[4];
    for (int o = 16; o; o >>= 1) s += __shfl_down_sync(0xffffffffu, s, o);
    if ((threadIdx.x & 31) == 0) sm[threadIdx.x >> 5] = s;
    __syncthreads();
    if (threadIdx.x == 0) {
        float v = sm[0] + sm[1] + sm[2] + sm[3];
        mask[bn] = v > 0.f ? 1.f : 0.f;
    }
}

__global__ void mean_kernel(const float* __restrict__ obj,
                            const float* __restrict__ mask,
                            float* __restrict__ mean)
{
    int idx = blockIdx.x * blockDim.x + threadIdx.x;
    int b = idx >> 11;
    int d = idx & (ND - 1);
    const float* mb = mask + b * NOBJ;
    const float* ob = obj + ((size_t)b * NOBJ) * ND + d;
    float acc = 0.f, cnt = 0.f;
#pragma unroll 4
    for (int n = 0; n < NOBJ; n++) {
        float m = mb[n];
        cnt += m;
        acc += ob[(size_t)n * ND] * m;
    }
    mean[idx] = acc / fmaxf(cnt, 1e-9f);
}

__global__ void build_Am(const float* __restrict__ qzm, const int* __restrict__ x,
                         const float* __restrict__ emb, float* __restrict__ Am)
{
    int r = blockIdx.x;
    int t = r % NT;
    int b = r / NT;
    float* out = Am + (size_t)r * KAM;
    const float* z = qzm + ((size_t)b * NT + (t - 1)) * NE;
    const float* e = emb + (size_t)x[r] * NEMB;
    for (int c = threadIdx.x; c < KAM; c += blockDim.x) {
        float v;
        if (c < NE)              v = (t == 0) ? 0.f : z[c];
        else if (c < NE + NEMB)  v = e[c - NE];
        else                     v = 0.f;
        out[c] = v;
    }
}

__global__ void build_Ao(const float* __restrict__ qzm, const float* __restrict__ qzo,
                         const int* __restrict__ x, const float* __restrict__ emb,
                         float* __restrict__ Ao)
{
    int r = blockIdx.x;
    int t = r % NT;
    int b = r / NT;
    float* out = Ao + (size_t)r * KAO;
    const float* zc = qzm + ((size_t)b * NT + t) * NE;
    const float* zp = qzo + ((size_t)b * NT + (t - 1)) * NE;
    const float* e  = emb + (size_t)x[r] * NEMB;
    for (int c = threadIdx.x; c < KAO; c += blockDim.x) {
        float v;
        if (c < NE)                    v = zc[c];
        else if (c < 2 * NE)           v = (t == 0) ? 0.f : zp[c - NE];
        else if (c < 2 * NE + NEMB)    v = e[c - 2 * NE];
        else                           v = 0.f;
        out[c] = v;
    }
}

__global__ void zero_state(float* hm, float* cm, float* ho, float* co)
{
    int idx = blockIdx.x * blockDim.x + threadIdx.x;
    if (idx < NB * NHM) { hm[idx] = 0.f; cm[idx] = 0.f; }
    if (idx < NB * NHO) { ho[idx] = 0.f; co[idx] = 0.f; }
}

__global__ void kl_kernel(const float* __restrict__ outm, const float* __restrict__ outo,
                          const float* __restrict__ qmm, const float* __restrict__ qlm,
                          const float* __restrict__ qmo, const float* __restrict__ qlo,
                          const int* __restrict__ x, float* __restrict__ out)
{
    int b = blockIdx.x;
    float acc = 0.f;
    for (int i = threadIdx.x; i < NT * NE; i += blockDim.x) {
        int t = i / NE;
        int e = i - t * NE;
        int tok = x[b * NT + t];
        if (tok == 0 || tok == 2) continue;
        size_t ro = (size_t)b * NT + t;
        size_t po = ro * (2 * NE);
        size_t qo = ro * NE + e;
        float pm = outm[po + e], pl = outm[po + NE + e];
        float qm = qmm[qo],      ql = qlm[qo];
        float dm = qm - pm;
        acc += 0.5f * (pl - ql) + (expf(ql) + dm * dm) / (2.f * expf(pl)) - 0.5f;
        pm = outo[po + e]; pl = outo[po + NE + e];
        qm = qmo[qo];      ql = qlo[qo];
        dm = qm - pm;
        acc += 0.5f * (pl - ql) + (expf(ql) + dm * dm) / (2.f * expf(pl)) - 0.5f;
    }
    __shared__ float sm[256];
    sm[threadIdx.x] = acc;
    __syncthreads();
    for (int s = 128; s; s >>= 1) {
        if (threadIdx.x < s) sm[threadIdx.x] += sm[threadIdx.x + s];
        __syncthreads();
    }
    if (threadIdx.x == 0) out[b] = sm[0];
}

// ---------------- host ----------------
extern "C" void kernel_launch(void* const* d_in, const int* in_sizes, int n_in,
                              void* d_out, int out_size)
{
    const float* obj_enc  = (const float*)d_in[0];
    const int*   x        = (const int*)  d_in[1];
    const float* qmm      = (const float*)d_in[2];
    const float* qlm      = (const float*)d_in[3];
    const float* qzm      = (const float*)d_in[4];
    const float* qmo      = (const float*)d_in[5];
    const float* qlo      = (const float*)d_in[6];
    const float* qzo      = (const float*)d_in[7];
    const float* emd_W    = (const float*)d_in[8];
    const float* W_ih_m   = (const float*)d_in[9];
    const float* W_hh_m   = (const float*)d_in[10];
    const float* b_m      = (const float*)d_in[11];
    const float* W_ih_o   = (const float*)d_in[12];
    const float* W_hh_o   = (const float*)d_in[13];
    const float* b_o      = (const float*)d_in[14];
    const float* fc_m_W   = (const float*)d_in[15];
    const float* fc_m_b   = (const float*)d_in[16];
    const float* fc_o_W   = (const float*)d_in[17];
    const float* fc_o_b   = (const float*)d_in[18];
    float* out = (float*)d_out;

    float* s = nullptr;
    cudaGetSymbolAddress((void**)&s, d_scratch);

    float* pMask = s + OFF_MASK;
    float* pMean = s + OFF_MEAN;
    float* pAm   = s + OFF_AM;
    float* pAo   = s + OFF_AO;
    float* pGm   = s + OFF_GM;
    float* pGo   = s + OFF_GO;
    float* pFm   = s + OFF_FM;
    float* pFo   = s + OFF_FO;
    float* pHmA  = s + OFF_HMA;
    float* pHmB  = s + OFF_HMB;
    float* pCm   = s + OFF_CM;
    float* pHoA  = s + OFF_HOA;
    float* pHoB  = s + OFF_HOB;
    float* pCo   = s + OFF_CO;
    float* pHms  = s + OFF_HMS;
    float* pHos  = s + OFF_HOS;
    float* pOutm = s + OFF_OUTM;
    float* pOuto = s + OFF_OUTO;
    float* pWIM  = s + OFF_WIM;
    float* pWIO  = s + OFF_WIO;
    float* pWHM  = s + OFF_WHM;
    float* pWHO  = s + OFF_WHO;
    float* pBM   = s + OFF_BM;
    float* pBO   = s + OFF_BO;

    // opt-in to >48KB dynamic smem (idempotent; first call precedes capture)
    cudaFuncSetAttribute(gemm_tf32, cudaFuncAttributeMaxDynamicSharedMemorySize, DYNSMEM);
    cudaFuncSetAttribute(lstm_step, cudaFuncAttributeMaxDynamicSharedMemorySize, DYNSMEM);

    // 1) object mask + mean image features
    objmask_kernel<<<NB * NOBJ, 128>>>(obj_enc, pMask);
    mean_kernel<<<(NB * ND) / 256, 256>>>(obj_enc, pMask, pMean);

    // 2) build batched LSTM input matrices
    build_Am<<<BT, 256>>>(qzm, x, emd_W, pAm);
    build_Ao<<<BT, 256>>>(qzm, qzo, x, emd_W, pAo);

    // 3) gate-interleave all LSTM weights + biases
    reorder_gates<<<GM4, 256>>>(W_ih_m, pWIM, NHM, LDW_M);
    reorder_gates<<<GO4, 256>>>(W_ih_o, pWIO, NHO, LDW_O);
    reorder_gates<<<GM4, 256>>>(W_hh_m, pWHM, NHM, NHM);
    reorder_gates<<<GO4, 256>>>(W_hh_o, pWHO, NHO, NHO);
    reorder_bias<<<(GM4 + 255) / 256, 256>>>(b_m, pBM, NHM);
    reorder_bias<<<(GO4 + 255) / 256, 256>>>(b_o, pBO, NHO);

    // 4) time-invariant feature contribution F = mean @ W_ih[:,feat]^T
    gemm_tf32<<<dim3(GM4 / 128, NB / 128), 256, DYNSMEM>>>(
        pMean, ND, pWIM + (NE + NEMB), LDW_M, pFm, GM4, ND, nullptr, nullptr, 1);
    gemm_tf32<<<dim3(GO4 / 128, NB / 128), 256, DYNSMEM>>>(
        pMean, ND, pWIO + (2 * NE + NEMB), LDW_O, pFo, GO4, ND, nullptr, nullptr, 1);

    // 5) G = A @ W_ih[:, :K]^T + bias + F[b]   (F folded in epilogue)
    gemm_tf32<<<dim3(GM4 / 128, BT / 128), 256, DYNSMEM>>>(
        pAm, KAM, pWIM, LDW_M, pGm, GM4, KAM, pBM, pFm, NT);
    gemm_tf32<<<dim3(GO4 / 128, BT / 128), 256, DYNSMEM>>>(
        pAo, KAO, pWIO, LDW_O, pGo, GO4, KAO, pBO, pFo, NT);

    // 6) init state (ping buffers + c)
    zero_state<<<(NB * NHM + 255) / 256, 256>>>(pHmA, pCm, pHoA, pCo);

    // 7) fused recurrence: one launch per step, both LSTMs, cell in epilogue
    for (int t = 0; t < NT; t++) {
        const float* hmi = (t & 1) ? pHmB : pHmA;
        float*       hmo = (t & 1) ? pHmA : pHmB;
        const float* hoi = (t & 1) ? pHoB : pHoA;
        float*       hoo = (t & 1) ? pHoA : pHoB;
        lstm_step<<<dim3(32, 4), 256, DYNSMEM>>>(
            hmi, hmo, pCm, pWHM, pGm, pHms,
            hoi, hoo, pCo, pWHO, pGo, pHos, t);
    }

    // 8) output FCs
    gemm_tf32<<<dim3((2 * NE) / 128, BT / 128), 256, DYNSMEM>>>(
        pHms, NHM, fc_m_W, NHM, pOutm, 2 * NE, NHM, fc_m_b, nullptr, 1);
    gemm_tf32<<<dim3((2 * NE) / 128, BT / 128), 256, DYNSMEM>>>(
        pHos, NHO, fc_o_W, NHO, pOuto, 2 * NE, NHO, fc_o_b, nullptr, 1);

    // 9) KL reduction
    kl_kernel<<<NB, 256>>>(pOutm, pOuto, qmm, qlm, qmo, qlo, x, out);
}

// round 6
// speedup vs baseline: 1.2378x; 1.2378x over previous
#include <cuda_runtime.h>
#include <cuda_bf16.h>
#include <math.h>

#define NB 512
#define NT 20
#define NOBJ 36
#define ND 2048
#define NEMB 300
#define NE 512
#define NHM 1024
#define NHO 256

constexpr int BT  = NB * NT;          // 10240
constexpr int KAM = 832;              // E+EMB=812 padded
constexpr int KAO = 1344;             // 2E+EMB=1324 padded
constexpr int GM4 = 4 * NHM;          // 4096
constexpr int GO4 = 4 * NHO;          // 1024
constexpr int LDW_M = NE + NEMB + ND;       // 2860
constexpr int LDW_O = 2 * NE + NEMB + ND;   // 3372
constexpr int KIN_M = NE + NEMB;            // 812
constexpr int KIN_O = 2 * NE + NEMB;        // 1324

// ---------------- scratch arena (float units; bf16 arrays cast) ----------
constexpr size_t OFF_MASK  = 0;
constexpr size_t OFF_MEANB = OFF_MASK  + (size_t)NB * NOBJ;          // bf16 NB*ND
constexpr size_t OFF_AM    = OFF_MEANB + (size_t)NB * ND / 2;        // bf16 BT*KAM
constexpr size_t OFF_AO    = OFF_AM    + (size_t)BT * KAM / 2;       // bf16 BT*KAO
constexpr size_t OFF_GM    = OFF_AO    + (size_t)BT * KAO / 2;       // f32
constexpr size_t OFF_GO    = OFF_GM    + (size_t)BT * GM4;
constexpr size_t OFF_FM    = OFF_GO    + (size_t)BT * GO4;
constexpr size_t OFF_FO    = OFF_FM    + (size_t)NB * GM4;
constexpr size_t OFF_HMA   = OFF_FO    + (size_t)NB * GO4;           // bf16
constexpr size_t OFF_HMB   = OFF_HMA   + (size_t)NB * NHM / 2;
constexpr size_t OFF_CM    = OFF_HMB   + (size_t)NB * NHM / 2;       // f32
constexpr size_t OFF_HOA   = OFF_CM    + (size_t)NB * NHM;
constexpr size_t OFF_HOB   = OFF_HOA   + (size_t)NB * NHO / 2;
constexpr size_t OFF_CO    = OFF_HOB   + (size_t)NB * NHO / 2;
constexpr size_t OFF_HMS   = OFF_CO    + (size_t)NB * NHO;           // bf16 BT*NHM
constexpr size_t OFF_HOS   = OFF_HMS   + (size_t)BT * NHM / 2;       // bf16
constexpr size_t OFF_OUTM  = OFF_HOS   + (size_t)BT * NHO / 2;       // f32
constexpr size_t OFF_OUTO  = OFF_OUTM  + (size_t)BT * 2 * NE;
constexpr size_t OFF_WIMIN = OFF_OUTO  + (size_t)BT * 2 * NE;        // bf16 GM4*KAM
constexpr size_t OFF_WIMFT = OFF_WIMIN + (size_t)GM4 * KAM / 2;      // bf16 GM4*ND
constexpr size_t OFF_WIOIN = OFF_WIMFT + (size_t)GM4 * ND / 2;
constexpr size_t OFF_WIOFT = OFF_WIOIN + (size_t)GO4 * KAO / 2;
constexpr size_t OFF_WHM   = OFF_WIOFT + (size_t)GO4 * ND / 2;       // bf16 GM4*NHM
constexpr size_t OFF_WHO   = OFF_WHM   + (size_t)GM4 * NHM / 2;
constexpr size_t OFF_FCM   = OFF_WHO   + (size_t)GO4 * NHO / 2;      // bf16 1024*NHM
constexpr size_t OFF_FCO   = OFF_FCM   + (size_t)1024 * NHM / 2;
constexpr size_t OFF_BM    = OFF_FCO   + (size_t)1024 * NHO / 2;     // f32
constexpr size_t OFF_BO    = OFF_BM    + GM4;
constexpr size_t TOTAL     = OFF_BO    + GO4;

__device__ float d_scratch[TOTAL];

typedef __nv_bfloat16 bf16;

// =====================================================================
// bf16 mma GEMM core: 128x128 block, k-tile 32 (2x m16n8k16), 8 warps
// 64x32. Fragment-major smem planes, stride 40 u32 (conflict-free LDS,
// 2-way max STS.128). Double buffered: 40KB static -> 2 CTAs/SM.
// =====================================================================
#define ABLK 40

struct __align__(16) SmemBuf {
    unsigned A[4][8 * 2 * ABLK];   // 4 frag-reg planes, 8 m-tiles x 2 ik
    unsigned B[2][16 * 2 * ABLK];  // 2 frag-reg planes, 16 n-tiles x 2 ik
};

__device__ __forceinline__ void mma_bf16(float* d, const unsigned* a, const unsigned* b) {
    asm volatile(
        "mma.sync.aligned.m16n8k16.row.col.f32.bf16.bf16.f32 "
        "{%0,%1,%2,%3},{%4,%5,%6,%7},{%8,%9},{%0,%1,%2,%3};"
        : "+f"(d[0]), "+f"(d[1]), "+f"(d[2]), "+f"(d[3])
        : "r"(a[0]), "r"(a[1]), "r"(a[2]), "r"(a[3]), "r"(b[0]), "r"(b[1]));
}

__device__ __forceinline__ void fill_tiles(SmemBuf* buf, int tid,
                                           const uint4* av, const uint4* bv)
{
#pragma unroll
    for (int q = 0; q < 2; q++) {
        int v = tid + q * 256;
        int r = v >> 2, f8 = v & 3;
        {
            int reg = ((r >> 3) & 1) + 2 * (f8 & 1);
            int off = ((r >> 4) * 2 + (f8 >> 1)) * ABLK + 4 * (r & 7);
            *(uint4*)&buf->A[reg][off] = av[q];
        }
        {
            int reg = f8 & 1;
            int off = ((r >> 3) * 2 + (f8 >> 1)) * ABLK + 4 * (r & 7);
            *(uint4*)&buf->B[reg][off] = bv[q];
        }
    }
}

// A: block-row base (128 rows), W: block-col base (128 rows). K % 32 == 0.
__device__ __forceinline__ void gemm_core_bf16(
    const bf16* __restrict__ A, int lda,
    const bf16* __restrict__ W, int ldw, int K,
    SmemBuf* sm, int tid, float acc[4][4][4])
{
    const int lane = tid & 31;
    const int w = tid >> 5, wm = w & 1, wn = w >> 1;

#pragma unroll
    for (int i = 0; i < 4; i++)
#pragma unroll
        for (int j = 0; j < 4; j++)
#pragma unroll
            for (int r = 0; r < 4; r++) acc[i][j][r] = 0.f;

    uint4 av[2], bv[2];
#pragma unroll
    for (int q = 0; q < 2; q++) {
        int v = tid + q * 256;
        int r = v >> 2, f8 = v & 3;
        av[q] = *(const uint4*)(A + (size_t)r * lda + 8 * f8);
        bv[q] = *(const uint4*)(W + (size_t)r * ldw + 8 * f8);
    }
    fill_tiles(&sm[0], tid, av, bv);
    __syncthreads();

    const int KT = K / 32;
    for (int kt = 0; kt < KT; kt++) {
        SmemBuf* b = &sm[kt & 1];
        const bool more = (kt + 1 < KT);
        if (more) {
            int k0 = (kt + 1) * 32;
#pragma unroll
            for (int q = 0; q < 2; q++) {
                int v = tid + q * 256;
                int r = v >> 2, f8 = v & 3;
                av[q] = *(const uint4*)(A + (size_t)r * lda + k0 + 8 * f8);
                bv[q] = *(const uint4*)(W + (size_t)r * ldw + k0 + 8 * f8);
            }
        }

#pragma unroll
        for (int ik = 0; ik < 2; ik++) {
            unsigned af[4][4], bfr[4][2];
#pragma unroll
            for (int il = 0; il < 4; il++) {
                int off = ((wm * 4 + il) * 2 + ik) * ABLK + lane;
                af[il][0] = b->A[0][off];
                af[il][1] = b->A[1][off];
                af[il][2] = b->A[2][off];
                af[il][3] = b->A[3][off];
            }
#pragma unroll
            for (int jl = 0; jl < 4; jl++) {
                int off = ((wn * 4 + jl) * 2 + ik) * ABLK + lane;
                bfr[jl][0] = b->B[0][off];
                bfr[jl][1] = b->B[1][off];
            }
#pragma unroll
            for (int il = 0; il < 4; il++)
#pragma unroll
                for (int jl = 0; jl < 4; jl++)
                    mma_bf16(acc[il][jl], af[il], bfr[jl]);
        }

        if (more) {
            fill_tiles(&sm[(kt + 1) & 1], tid, av, bv);
            __syncthreads();
        }
    }
}

// ---------------- standalone GEMM: C = A@W^T (+bias) (+F[row/fdiv]) -----
__global__ __launch_bounds__(256, 2) void gemm_bf16(
    const bf16* __restrict__ A, int lda,
    const bf16* __restrict__ W, int ldw,
    float* __restrict__ C, int ldc, int K,
    const float* __restrict__ bias,
    const float* __restrict__ F, int fdiv)
{
    __shared__ SmemBuf sm[2];
    const int tid = threadIdx.x;
    const int lane = tid & 31;
    const int w = tid >> 5, wm = w & 1, wn = w >> 1;
    const long bm = (long)blockIdx.y * 128;
    const long bn = (long)blockIdx.x * 128;

    float acc[4][4][4];
    gemm_core_bf16(A + bm * (size_t)lda, lda, W + bn * (size_t)ldw, ldw,
                   K, sm, tid, acc);

    const int g = lane >> 2;
    const int cp = (lane & 3) * 2;
#pragma unroll
    for (int jl = 0; jl < 4; jl++) {
        long col = bn + wn * 32 + jl * 8 + cp;
        float b0 = 0.f, b1 = 0.f;
        if (bias) { b0 = bias[col]; b1 = bias[col + 1]; }
#pragma unroll
        for (int il = 0; il < 4; il++) {
            long row = bm + wm * 64 + il * 16 + g;
            float a0 = b0, a1 = b1, a2 = b0, a3 = b1;
            if (F) {
                long fb0 = row / fdiv, fb1 = (row + 8) / fdiv;
                a0 += F[fb0 * ldc + col];  a1 += F[fb0 * ldc + col + 1];
                a2 += F[fb1 * ldc + col];  a3 += F[fb1 * ldc + col + 1];
            }
            *(float2*)(C + row * (long)ldc + col) =
                make_float2(acc[il][jl][0] + a0, acc[il][jl][1] + a1);
            *(float2*)(C + (row + 8) * (long)ldc + col) =
                make_float2(acc[il][jl][2] + a2, acc[il][jl][3] + a3);
        }
    }
}

// ---------------- fused LSTM step ----------------
__device__ __forceinline__ float tfast(float x) {
    float y;
    asm("tanh.approx.f32 %0, %1;" : "=f"(y) : "f"(x));
    return y;
}
__device__ __forceinline__ float sigf(float x) { return 0.5f * tfast(0.5f * x) + 0.5f; }

// shfl-based cell epilogue: adjacent lanes exchange gate pairs so each
// thread owns all 4 (interleaved) gates of one unit for one row.
__device__ __forceinline__ void cell_epi(
    float acc[4][4][4], int tid,
    const float* __restrict__ G, float* __restrict__ c,
    bf16* __restrict__ hout, bf16* __restrict__ Hseq,
    long bm, int bx, int H, int t)
{
    const int lane = tid & 31;
    const int w = tid >> 5, wm = w & 1, wn = w >> 1;
    const int g = lane >> 2;
    const bool odd = lane & 1;
    const int H4 = 4 * H;

#pragma unroll
    for (int il = 0; il < 4; il++) {
        long row = bm + wm * 64 + il * 16 + g + (odd ? 8 : 0);
#pragma unroll
        for (int jl = 0; jl < 4; jl++) {
            float s0 = odd ? acc[il][jl][0] : acc[il][jl][2];
            float s1 = odd ? acc[il][jl][1] : acc[il][jl][3];
            float r0 = __shfl_xor_sync(0xffffffffu, s0, 1);
            float r1 = __shfl_xor_sync(0xffffffffu, s1, 1);
            float gi, gf, gg, go;
            if (!odd) { gi = acc[il][jl][0]; gf = acc[il][jl][1]; gg = r0; go = r1; }
            else      { gi = r0; gf = r1; gg = acc[il][jl][2]; go = acc[il][jl][3]; }

            int ul = wn * 8 + jl * 2 + ((lane & 2) >> 1);
            const float4 G4 = *(const float4*)&G[(row * NT + t) * (size_t)H4
                                                + (size_t)bx * 128 + ul * 4];
            gi += G4.x; gf += G4.y; gg += G4.z; go += G4.w;

            int u = bx * 32 + ul;
            size_t si = (size_t)row * H + u;
            float cn = sigf(gf) * c[si] + sigf(gi) * tfast(gg);
            float hn = sigf(go) * tfast(cn);
            c[si] = cn;
            bf16 hb = __float2bfloat16(hn);
            hout[si] = hb;
            Hseq[(row * NT + t) * (size_t)H + u] = hb;
        }
    }
}

__global__ __launch_bounds__(256, 2) void lstm_step(
    const bf16* __restrict__ hmi, bf16* __restrict__ hmo, float* __restrict__ cm,
    const bf16* __restrict__ Whm, const float* __restrict__ Gm, bf16* __restrict__ Hms,
    const bf16* __restrict__ hoi, bf16* __restrict__ hoo, float* __restrict__ co,
    const bf16* __restrict__ Who, const float* __restrict__ Go, bf16* __restrict__ Hos,
    int t)
{
    __shared__ SmemBuf sm[2];
    const int tid = threadIdx.x;
    const int id = blockIdx.x;           // 0..159
    float acc[4][4][4];

    if (id < 128) {                      // m-LSTM: 32 col-tiles x 4 row-tiles
        int bx = id & 31;
        long bm = (long)(id >> 5) * 128;
        gemm_core_bf16(hmi + bm * NHM, NHM, Whm + (size_t)bx * 128 * NHM, NHM,
                       NHM, sm, tid, acc);
        cell_epi(acc, tid, Gm, cm, hmo, Hms, bm, bx, NHM, t);
    } else {                             // o-LSTM: 8 col-tiles x 4 row-tiles
        int r = id - 128;
        int bx = r & 7;
        long bm = (long)(r >> 3) * 128;
        gemm_core_bf16(hoi + bm * NHO, NHO, Who + (size_t)bx * 128 * NHO, NHO,
                       NHO, sm, tid, acc);
        cell_epi(acc, tid, Go, co, hoo, Hos, bm, bx, NHO, t);
    }
}

// ---------------- setup kernels (bf16 conversion + reorders) -------------
__global__ void objmask_kernel(const float* __restrict__ obj, float* __restrict__ mask)
{
    int bn = blockIdx.x;
    const float* p = obj + (size_t)bn * ND;
    float s = 0.f;
    for (int d = threadIdx.x; d < ND; d += blockDim.x) s += fabsf(p[d]);
    __shared__ float sm[4];
    for (int o = 16; o; o >>= 1) s += __shfl_down_sync(0xffffffffu, s, o);
    if ((threadIdx.x & 31) == 0) sm[threadIdx.x >> 5] = s;
    __syncthreads();
    if (threadIdx.x == 0)
        mask[bn] = (sm[0] + sm[1] + sm[2] + sm[3]) > 0.f ? 1.f : 0.f;
}

__global__ void mean_kernel(const float* __restrict__ obj,
                            const float* __restrict__ mask,
                            bf16* __restrict__ meanb)
{
    int idx = blockIdx.x * blockDim.x + threadIdx.x;
    int b = idx >> 11;
    int d = idx & (ND - 1);
    const float* mb = mask + b * NOBJ;
    const float* ob = obj + ((size_t)b * NOBJ) * ND + d;
    float acc = 0.f, cnt = 0.f;
#pragma unroll 4
    for (int n = 0; n < NOBJ; n++) {
        float m = mb[n];
        cnt += m;
        acc += ob[(size_t)n * ND] * m;
    }
    meanb[idx] = __float2bfloat16(acc / fmaxf(cnt, 1e-9f));
}

__global__ void build_Am(const float* __restrict__ qzm, const int* __restrict__ x,
                         const float* __restrict__ emb, bf16* __restrict__ Am)
{
    int r = blockIdx.x;
    int t = r % NT, b = r / NT;
    bf16* out = Am + (size_t)r * KAM;
    const float* z = qzm + ((size_t)b * NT + (t - 1)) * NE;
    const float* e = emb + (size_t)x[r] * NEMB;
    for (int c = threadIdx.x; c < KAM; c += blockDim.x) {
        float v;
        if (c < NE)              v = (t == 0) ? 0.f : z[c];
        else if (c < NE + NEMB)  v = e[c - NE];
        else                     v = 0.f;
        out[c] = __float2bfloat16(v);
    }
}

__global__ void build_Ao(const float* __restrict__ qzm, const float* __restrict__ qzo,
                         const int* __restrict__ x, const float* __restrict__ emb,
                         bf16* __restrict__ Ao)
{
    int r = blockIdx.x;
    int t = r % NT, b = r / NT;
    bf16* out = Ao + (size_t)r * KAO;
    const float* zc = qzm + ((size_t)b * NT + t) * NE;
    const float* zp = qzo + ((size_t)b * NT + (t - 1)) * NE;
    const float* e  = emb + (size_t)x[r] * NEMB;
    for (int c = threadIdx.x; c < KAO; c += blockDim.x) {
        float v;
        if (c < NE)                 v = zc[c];
        else if (c < 2 * NE)        v = (t == 0) ? 0.f : zp[c - NE];
        else if (c < 2 * NE + NEMB) v = e[c - 2 * NE];
        else                        v = 0.f;
        out[c] = __float2bfloat16(v);
    }
}

// W_ih split reorder: dst row 4u+g <- src row g*H+u; in-part (kin cols,
// zero-padded to ldin) and feat-part (ND cols), both bf16.
__global__ void reorder_ih(const float* __restrict__ src, int ldsrc, int kin,
                           bf16* __restrict__ din, int ldin,
                           bf16* __restrict__ dft, int H)
{
    int r = blockIdx.x;
    int u = r >> 2, g = r & 3;
    const float* s = src + (size_t)(g * H + u) * ldsrc;
    bf16* a = din + (size_t)r * ldin;
    bf16* b = dft + (size_t)r * ND;
    for (int c = threadIdx.x; c < ldin; c += blockDim.x)
        a[c] = __float2bfloat16(c < kin ? s[c] : 0.f);
    for (int c = threadIdx.x; c < ND; c += blockDim.x)
        b[c] = __float2bfloat16(s[kin + c]);
}

__global__ void reorder_hh(const float* __restrict__ src, bf16* __restrict__ dst, int H)
{
    int r = blockIdx.x;
    int u = r >> 2, g = r & 3;
    const float* s = src + (size_t)(g * H + u) * H;
    bf16* d = dst + (size_t)r * H;
    for (int c = threadIdx.x; c < H; c += blockDim.x)
        d[c] = __float2bfloat16(s[c]);
}

__global__ void reorder_bias(const float* __restrict__ src, float* __restrict__ dst, int H)
{
    int r = blockIdx.x * blockDim.x + threadIdx.x;
    if (r < 4 * H) { int u = r >> 2, g = r & 3; dst[r] = src[g * H + u]; }
}

__global__ void f2bf_kernel(const float* __restrict__ s, bf16* __restrict__ d, int n)
{
    int i = blockIdx.x * blockDim.x + threadIdx.x;
    if (i < n) d[i] = __float2bfloat16(s[i]);
}

__global__ void zero_state(bf16* hm, float* cm, bf16* ho, float* co)
{
    int idx = blockIdx.x * blockDim.x + threadIdx.x;
    if (idx < NB * NHM) { hm[idx] = __float2bfloat16(0.f); cm[idx] = 0.f; }
    if (idx < NB * NHO) { ho[idx] = __float2bfloat16(0.f); co[idx] = 0.f; }
}

__global__ void kl_kernel(const float* __restrict__ outm, const float* __restrict__ outo,
                          const float* __restrict__ qmm, const float* __restrict__ qlm,
                          const float* __restrict__ qmo, const float* __restrict__ qlo,
                          const int* __restrict__ x, float* __restrict__ out)
{
    int b = blockIdx.x;
    float acc = 0.f;
    for (int i = threadIdx.x; i < NT * NE; i += blockDim.x) {
        int t = i / NE;
        int e = i - t * NE;
        int tok = x[b * NT + t];
        if (tok == 0 || tok == 2) continue;
        size_t ro = (size_t)b * NT + t;
        size_t po = ro * (2 * NE);
        size_t qo = ro * NE + e;
        float pm = outm[po + e], pl = outm[po + NE + e];
        float qm = qmm[qo],      ql = qlm[qo];
        float dm = qm - pm;
        acc += 0.5f * (pl - ql) + (expf(ql) + dm * dm) / (2.f * expf(pl)) - 0.5f;
        pm = outo[po + e]; pl = outo[po + NE + e];
        qm = qmo[qo];      ql = qlo[qo];
        dm = qm - pm;
        acc += 0.5f * (pl - ql) + (expf(ql) + dm * dm) / (2.f * expf(pl)) - 0.5f;
    }
    __shared__ float sm[256];
    sm[threadIdx.x] = acc;
    __syncthreads();
    for (int s = 128; s; s >>= 1) {
        if (threadIdx.x < s) sm[threadIdx.x] += sm[threadIdx.x + s];
        __syncthreads();
    }
    if (threadIdx.x == 0) out[b] = sm[0];
}

// ---------------- host ----------------
extern "C" void kernel_launch(void* const* d_in, const int* in_sizes, int n_in,
                              void* d_out, int out_size)
{
    const float* obj_enc = (const float*)d_in[0];
    const int*   x       = (const int*)  d_in[1];
    const float* qmm     = (const float*)d_in[2];
    const float* qlm     = (const float*)d_in[3];
    const float* qzm     = (const float*)d_in[4];
    const float* qmo     = (const float*)d_in[5];
    const float* qlo     = (const float*)d_in[6];
    const float* qzo     = (const float*)d_in[7];
    const float* emd_W   = (const float*)d_in[8];
    const float* W_ih_m  = (const float*)d_in[9];
    const float* W_hh_m  = (const float*)d_in[10];
    const float* b_m     = (const float*)d_in[11];
    const float* W_ih_o  = (const float*)d_in[12];
    const float* W_hh_o  = (const float*)d_in[13];
    const float* b_o     = (const float*)d_in[14];
    const float* fc_m_W  = (const float*)d_in[15];
    const float* fc_m_b  = (const float*)d_in[16];
    const float* fc_o_W  = (const float*)d_in[17];
    const float* fc_o_b  = (const float*)d_in[18];
    float* out = (float*)d_out;

    float* s = nullptr;
    cudaGetSymbolAddress((void**)&s, d_scratch);

    float* pMask  = s + OFF_MASK;
    bf16*  pMeanB = (bf16*)(s + OFF_MEANB);
    bf16*  pAm    = (bf16*)(s + OFF_AM);
    bf16*  pAo    = (bf16*)(s + OFF_AO);
    float* pGm    = s + OFF_GM;
    float* pGo    = s + OFF_GO;
    float* pFm    = s + OFF_FM;
    float* pFo    = s + OFF_FO;
    bf16*  pHmA   = (bf16*)(s + OFF_HMA);
    bf16*  pHmB   = (bf16*)(s + OFF_HMB);
    float* pCm    = s + OFF_CM;
    bf16*  pHoA   = (bf16*)(s + OFF_HOA);
    bf16*  pHoB   = (bf16*)(s + OFF_HOB);
    float* pCo    = s + OFF_CO;
    bf16*  pHms   = (bf16*)(s + OFF_HMS);
    bf16*  pHos   = (bf16*)(s + OFF_HOS);
    float* pOutm  = s + OFF_OUTM;
    float* pOuto  = s + OFF_OUTO;
    bf16*  pWIMin = (bf16*)(s + OFF_WIMIN);
    bf16*  pWIMft = (bf16*)(s + OFF_WIMFT);
    bf16*  pWIOin = (bf16*)(s + OFF_WIOIN);
    bf16*  pWIOft = (bf16*)(s + OFF_WIOFT);
    bf16*  pWHM   = (bf16*)(s + OFF_WHM);
    bf16*  pWHO   = (bf16*)(s + OFF_WHO);
    bf16*  pFCM   = (bf16*)(s + OFF_FCM);
    bf16*  pFCO   = (bf16*)(s + OFF_FCO);
    float* pBM    = s + OFF_BM;
    float* pBO    = s + OFF_BO;

    // 1) object mask + mean image features (bf16 out)
    objmask_kernel<<<NB * NOBJ, 128>>>(obj_enc, pMask);
    mean_kernel<<<(NB * ND) / 256, 256>>>(obj_enc, pMask, pMeanB);

    // 2) batched LSTM input matrices (bf16)
    build_Am<<<BT, 256>>>(qzm, x, emd_W, pAm);
    build_Ao<<<BT, 256>>>(qzm, qzo, x, emd_W, pAo);

    // 3) weight reorders/conversions (bf16, gate-interleaved, split in/feat)
    reorder_ih<<<GM4, 256>>>(W_ih_m, LDW_M, KIN_M, pWIMin, KAM, pWIMft, NHM);
    reorder_ih<<<GO4, 256>>>(W_ih_o, LDW_O, KIN_O, pWIOin, KAO, pWIOft, NHO);
    reorder_hh<<<GM4, 256>>>(W_hh_m, pWHM, NHM);
    reorder_hh<<<GO4, 256>>>(W_hh_o, pWHO, NHO);
    reorder_bias<<<(GM4 + 255) / 256, 256>>>(b_m, pBM, NHM);
    reorder_bias<<<(GO4 + 255) / 256, 256>>>(b_o, pBO, NHO);
    f2bf_kernel<<<(1024 * NHM + 255) / 256, 256>>>(fc_m_W, pFCM, 1024 * NHM);
    f2bf_kernel<<<(1024 * NHO + 255) / 256, 256>>>(fc_o_W, pFCO, 1024 * NHO);

    // 4) time-invariant feature contribution
    gemm_bf16<<<dim3(GM4 / 128, NB / 128), 256>>>(
        pMeanB, ND, pWIMft, ND, pFm, GM4, ND, nullptr, nullptr, 1);
    gemm_bf16<<<dim3(GO4 / 128, NB / 128), 256>>>(
        pMeanB, ND, pWIOft, ND, pFo, GO4, ND, nullptr, nullptr, 1);

    // 5) G = A @ W_in^T + bias + F[b]
    gemm_bf16<<<dim3(GM4 / 128, BT / 128), 256>>>(
        pAm, KAM, pWIMin, KAM, pGm, GM4, KAM, pBM, pFm, NT);
    gemm_bf16<<<dim3(GO4 / 128, BT / 128), 256>>>(
        pAo, KAO, pWIOin, KAO, pGo, GO4, KAO, pBO, pFo, NT);

    // 6) init state
    zero_state<<<(NB * NHM + 255) / 256, 256>>>(pHmA, pCm, pHoA, pCo);

    // 7) fused recurrence, 160 balanced blocks per step
    for (int t = 0; t < NT; t++) {
        const bf16* hmi = (t & 1) ? pHmB : pHmA;
        bf16*       hmo = (t & 1) ? pHmA : pHmB;
        const bf16* hoi = (t & 1) ? pHoB : pHoA;
        bf16*       hoo = (t & 1) ? pHoA : pHoB;
        lstm_step<<<160, 256>>>(hmi, hmo, pCm, pWHM, pGm, pHms,
                                hoi, hoo, pCo, pWHO, pGo, pHos, t);
    }

    // 8) output FCs
    gemm_bf16<<<dim3((2 * NE) / 128, BT / 128), 256>>>(
        pHms, NHM, pFCM, NHM, pOutm, 2 * NE, NHM, fc_m_b, nullptr, 1);
    gemm_bf16<<<dim3((2 * NE) / 128, BT / 128), 256>>>(
        pHos, NHO, pFCO, NHO, pOuto, 2 * NE, NHO, fc_o_b, nullptr, 1);

    // 9) KL reduction
    kl_kernel<<<NB, 256>>>(pOutm, pOuto, qmm, qlm, qmo, qlo, x, out);
}